// round 4
// baseline (speedup 1.0000x reference)
#include <cuda_runtime.h>
#include <cuda_bf16.h>
#include <cstdint>

#define BB 512
#define LL 512
#define NN 128
#define RB 8            // real batches per block
#define PITCH 136       // bf16 elems per psh row (272B, conflict-free for ldmatrix)

__device__ float g_norm[BB];
__device__ float g_path[BB];

__device__ __forceinline__ uint32_t smem_u32(const void* p) {
    uint32_t a;
    asm("{ .reg .u64 t; cvta.to.shared.u64 t, %1; cvt.u32.u64 %0, t; }"
        : "=r"(a) : "l"(p));
    return a;
}
__device__ __forceinline__ uint32_t bfpack(float lo, float hi) {
    uint32_t d;
    asm("cvt.rn.bf16x2.f32 %0, %1, %2;" : "=r"(d) : "f"(hi), "f"(lo));
    return d;
}
__device__ __forceinline__ void ldm4(uint32_t& a0, uint32_t& a1,
                                     uint32_t& a2, uint32_t& a3, uint32_t addr) {
    asm volatile("ldmatrix.sync.aligned.m8n8.x4.shared.b16 {%0,%1,%2,%3}, [%4];"
                 : "=r"(a0), "=r"(a1), "=r"(a2), "=r"(a3) : "r"(addr));
}
__device__ __forceinline__ void mma16816(float& d0, float& d1, float& d2, float& d3,
                                         uint32_t a0, uint32_t a1, uint32_t a2, uint32_t a3,
                                         uint32_t b0, uint32_t b1) {
    asm volatile("mma.sync.aligned.m16n8k16.row.col.f32.bf16.bf16.f32 "
                 "{%0,%1,%2,%3},{%4,%5,%6,%7},{%8,%9},{%0,%1,%2,%3};"
                 : "+f"(d0), "+f"(d1), "+f"(d2), "+f"(d3)
                 : "r"(a0), "r"(a1), "r"(a2), "r"(a3), "r"(b0), "r"(b1));
}

// ---------------------------------------------------------------------------
// Forward: 64 blocks x 512 threads. Block = 8 batches (rows 0-7; 8-15 pad=0).
// C[16 x 128] = P[16 x 128] @ E[128 x 128], bf16 MMA, E frags in registers.
// Linear-domain recurrence: q_t = tot_t * exp(em_t) * inv_t, L += -log(inv).
// One __syncthreads per step; p double-buffered in smem.
// ---------------------------------------------------------------------------
__global__ __launch_bounds__(512, 1)
void crf_forward(const float* __restrict__ em,
                 const float* __restrict__ mask,
                 const float* __restrict__ start,
                 const float* __restrict__ trans) {
    __shared__ __align__(16) __nv_bfloat16 psh[2][16 * PITCH];
    __shared__ float rinv[2][RB];
    __shared__ float Lsh[RB];
    __shared__ float csh[RB];
    __shared__ float sred[RB][NN];

    const int tid  = threadIdx.x;
    const int w    = tid >> 5;          // warp 0..15 -> cols [8w, 8w+8)
    const int lane = tid & 31;
    const int r    = lane >> 2;         // C-frag row 0..7 (real batch row)
    const int c2   = lane & 3;
    const int jn   = 8 * w + 2 * c2;    // this thread's C cols: jn, jn+1
    const int b0   = blockIdx.x * RB;
    const int b    = b0 + r;

    // ---- B fragments: E[k][j] = exp(trans[k][j]), resident forever ----
    uint32_t Bf0[8], Bf1[8];
    {
        const int jB = 8 * w + (lane >> 2);   // B-frag col = lane/4
        const int kb = 2 * (lane & 3);
#pragma unroll
        for (int kk = 0; kk < 8; kk++) {
            int k0 = 16 * kk + kb;
            float e00 = __expf(trans[(k0)*NN + jB]);
            float e01 = __expf(trans[(k0 + 1) * NN + jB]);
            float e10 = __expf(trans[(k0 + 8) * NN + jB]);
            float e11 = __expf(trans[(k0 + 9) * NN + jB]);
            Bf0[kk] = bfpack(e00, e01);
            Bf1[kk] = bfpack(e10, e11);
        }
    }

    // ---- zero both p buffers (covers pad rows permanently) ----
    for (int i = tid; i < 2 * 16 * PITCH / 2; i += 512)
        ((uint32_t*)psh)[i] = 0u;

    // ---- init q0 = exp(s0 - s0[0]) ----
    const uint32_t psb = smem_u32(&psh[0][0]);
    float qA0, qA1;
    {
        float2 e0 = *(const float2*)&em[((size_t)b * LL) * NN + jn];
        float s00 = start[jn] + e0.x;
        float s01 = start[jn + 1] + e0.y;
        if (w == 0 && c2 == 0) { csh[r] = s00; Lsh[r] = s00; }
        __syncthreads();
        float c0 = csh[r];
        qA0 = __expf(s00 - c0);
        qA1 = __expf(s01 - c0);
        // step t=1 reads buffer 1
        *(uint32_t*)((char*)psh + (16 * PITCH * 2) + r * (PITCH * 2) + jn * 2)
            = bfpack(qA0, qA1);
        if (w == 0 && c2 == 0) rinv[1][r] = 1.0f / qA0;
    }

    // ---- prefetch t=1 ----
    float2 emv = *(const float2*)&em[((size_t)b * LL + 1) * NN + jn];
    float mk = mask[b * LL + 1];
    __syncthreads();

    for (int t = 1; t < LL; t++) {
        const int pr = t & 1, pw = pr ^ 1;

        // prefetch t+1
        float2 emn = make_float2(0.f, 0.f);
        float mkn = 1.0f;
        if (t + 1 < LL) {
            emn = *(const float2*)&em[((size_t)b * LL + t + 1) * NN + jn];
            mkn = mask[b * LL + t + 1];
        }

        // ---- MMA: tot = P @ E  (two accumulator chains) ----
        float d0 = 0.f, d1 = 0.f, dx0 = 0.f, dx1 = 0.f;
        float t2, t3;   // pad-row outputs (discarded)
        {
            float e2a = 0.f, e3a = 0.f, e2b = 0.f, e3b = 0.f;
            uint32_t abase = psb + (uint32_t)pr * (16 * PITCH * 2)
                           + (lane & 15) * (PITCH * 2) + (lane >> 4) * 16;
#pragma unroll
            for (int kk = 0; kk < 8; kk += 2) {
                uint32_t a0, a1, a2, a3;
                ldm4(a0, a1, a2, a3, abase + kk * 32);
                mma16816(d0, d1, e2a, e3a, a0, a1, a2, a3, Bf0[kk], Bf1[kk]);
                uint32_t c0_, c1_, c2_, c3_;
                ldm4(c0_, c1_, c2_, c3_, abase + (kk + 1) * 32);
                mma16816(dx0, dx1, e2b, e3b, c0_, c1_, c2_, c3_, Bf0[kk + 1], Bf1[kk + 1]);
            }
            d0 += dx0; d1 += dx1;
            t2 = e2a; t3 = e3a;  (void)t2; (void)t3; (void)e2b; (void)e3b;
        }

        // ---- epilogue ----
        float inv = rinv[pr][r];                 // 1/q_{t-1}[b][0]
        float ee0 = __expf(emv.x);
        float ee1 = __expf(emv.y);
        float qc0 = d0 * ee0 * inv;
        float qc1 = d1 * ee1 * inv;
        float q0, q1;
        if (mk == 1.0f) {
            q0 = qc0; q1 = qc1;
        } else if (mk == 0.0f) {
            q0 = qA0 * inv; q1 = qA1 * inv;
        } else {
            q0 = __expf(mk * __logf(qc0) + (1.0f - mk) * __logf(qA0 * inv));
            q1 = __expf(mk * __logf(qc1) + (1.0f - mk) * __logf(qA1 * inv));
        }
        qA0 = q0; qA1 = q1;

        if (w == 0 && c2 == 0) {
            Lsh[r] -= __logf(inv);               // L += log(q_{t-1}[0])
            rinv[pw][r] = 1.0f / q0;
        }
        *(uint32_t*)((char*)psh + (uint32_t)pw * (16 * PITCH * 2)
                     + r * (PITCH * 2) + jn * 2) = bfpack(q0, q1);

        emv = emn; mk = mkn;
        __syncthreads();
    }

    // ---- final: normalizer[b] = L[b] + log(sum_j q[b][j]) ----
    sred[r][jn]     = qA0;
    sred[r][jn + 1] = qA1;
    __syncthreads();
    if (w < RB) {
        float s = sred[w][lane] + sred[w][lane + 32] +
                  sred[w][lane + 64] + sred[w][lane + 96];
#pragma unroll
        for (int o = 16; o; o >>= 1)
            s += __shfl_xor_sync(0xffffffffu, s, o);
        if (lane == 0) g_norm[b0 + w] = Lsh[w] + __logf(s);
    }
}

// ---------------------------------------------------------------------------
// Path score. One block (128 threads) per batch.
// ---------------------------------------------------------------------------
__global__ __launch_bounds__(128)
void crf_path(const float* __restrict__ em,
              const int*   __restrict__ tgt,
              const float* __restrict__ mask,
              const float* __restrict__ start,
              const float* __restrict__ trans) {
    const int bb = blockIdx.x;
    const int tid = threadIdx.x;
    __shared__ float red[128];

    const size_t embase = (size_t)bb * LL * NN;
    float s = 0.0f;
    for (int t = tid; t < LL; t += 128) {
        if (t == 0) {
            int t0 = tgt[bb * LL];
            s += start[t0] + em[embase + t0];
        } else {
            int prev = tgt[bb * LL + t - 1];
            int cur  = tgt[bb * LL + t];
            s += mask[bb * LL + t] *
                 (trans[prev * NN + cur] + em[embase + (size_t)t * NN + cur]);
        }
    }
    red[tid] = s;
    __syncthreads();
#pragma unroll
    for (int o = 64; o; o >>= 1) {
        if (tid < o) red[tid] += red[tid + o];
        __syncthreads();
    }
    if (tid == 0) g_path[bb] = red[0];
}

// ---------------------------------------------------------------------------
// mean(normalizer - path)
// ---------------------------------------------------------------------------
__global__ __launch_bounds__(512)
void crf_final(float* __restrict__ out) {
    const int tid = threadIdx.x;
    __shared__ float wsum[16];
    float v = g_norm[tid] - g_path[tid];
#pragma unroll
    for (int o = 16; o; o >>= 1) v += __shfl_xor_sync(0xffffffffu, v, o);
    if ((tid & 31) == 0) wsum[tid >> 5] = v;
    __syncthreads();
    if (tid < 32) {
        float x = (tid < 16) ? wsum[tid] : 0.0f;
#pragma unroll
        for (int o = 8; o; o >>= 1) x += __shfl_xor_sync(0xffffffffu, x, o);
        if (tid == 0) out[0] = x * (1.0f / (float)BB);
    }
}

// ---------------------------------------------------------------------------
// Launch
// ---------------------------------------------------------------------------
extern "C" void kernel_launch(void* const* d_in, const int* in_sizes, int n_in,
                              void* d_out, int out_size) {
    const float* emission    = (const float*)d_in[0];
    const int*   target      = (const int*)  d_in[1];
    const float* mask        = (const float*)d_in[2];
    const float* start_trans = (const float*)d_in[3];
    const float* trans       = (const float*)d_in[4];
    float* out = (float*)d_out;

    crf_forward<<<BB / RB, 512>>>(emission, mask, start_trans, trans);
    crf_path<<<BB, 128>>>(emission, target, mask, start_trans, trans);
    crf_final<<<1, 512>>>(out);
}

// round 5
// speedup vs baseline: 1.6134x; 1.6134x over previous
#include <cuda_runtime.h>
#include <cuda_bf16.h>
#include <cstdint>

#define BB 512
#define LL 512
#define NN 128
#define RB 4            // real batches per block (rows 0..3 of the 16-row tile)
#define PITCH 136       // bf16 elems per psh row (272B)
#define ROWB (PITCH * 2)
#define BUFB (16 * ROWB)

__device__ float g_norm[BB];
__device__ float g_path[BB];

__device__ __forceinline__ uint32_t smem_u32(const void* p) {
    uint32_t a;
    asm("{ .reg .u64 t; cvta.to.shared.u64 t, %1; cvt.u32.u64 %0, t; }"
        : "=r"(a) : "l"(p));
    return a;
}
__device__ __forceinline__ uint32_t bfpack(float lo, float hi) {
    uint32_t d;
    asm("cvt.rn.bf16x2.f32 %0, %1, %2;" : "=r"(d) : "f"(hi), "f"(lo));
    return d;
}
__device__ __forceinline__ void ldm4(uint32_t& a0, uint32_t& a1,
                                     uint32_t& a2, uint32_t& a3, uint32_t addr) {
    asm volatile("ldmatrix.sync.aligned.m8n8.x4.shared.b16 {%0,%1,%2,%3}, [%4];"
                 : "=r"(a0), "=r"(a1), "=r"(a2), "=r"(a3) : "r"(addr));
}
__device__ __forceinline__ void mma16816(float& d0, float& d1, float& d2, float& d3,
                                         uint32_t a0, uint32_t a1, uint32_t a2, uint32_t a3,
                                         uint32_t b0, uint32_t b1) {
    asm volatile("mma.sync.aligned.m16n8k16.row.col.f32.bf16.bf16.f32 "
                 "{%0,%1,%2,%3},{%4,%5,%6,%7},{%8,%9},{%0,%1,%2,%3};"
                 : "+f"(d0), "+f"(d1), "+f"(d2), "+f"(d3)
                 : "r"(a0), "r"(a1), "r"(a2), "r"(a3), "r"(b0), "r"(b1));
}

// ---------------------------------------------------------------------------
// Forward: 128 blocks x 256 threads. Block = 4 batches (tile rows 0-3 real).
// C[16 x 128] = P[16 x 128] @ E[128 x 128]; warp w owns cols [16w, 16w+16)
// (two n-tiles), E fragments resident in registers, K-chains split even/odd.
// Linear-domain recurrence (one log per batch per step via stale q[0]).
// One __syncthreads per step; p double-buffered in smem.
// ---------------------------------------------------------------------------
__global__ __launch_bounds__(256, 1)
void crf_forward(const float* __restrict__ em,
                 const float* __restrict__ mask,
                 const float* __restrict__ start,
                 const float* __restrict__ trans) {
    __shared__ __align__(16) __nv_bfloat16 psh[2][16 * PITCH];
    __shared__ float rinv[2][RB];
    __shared__ float Lsh[RB];
    __shared__ float csh[RB];
    __shared__ float sred[RB][NN];

    const int tid  = threadIdx.x;
    const int w    = tid >> 5;          // warp 0..7 -> cols [16w, 16w+16)
    const int lane = tid & 31;
    const int r    = lane >> 2;         // C-frag row (real batch if r < 4)
    const int c2   = lane & 3;
    const int jn0  = 16 * w + 2 * c2;       // tile0 cols: jn0, jn0+1
    const int jn1  = jn0 + 8;               // tile1 cols
    const int b0   = blockIdx.x * RB;
    const bool real = (r < RB);
    const int b    = b0 + (real ? r : 0);

    // ---- B fragments: E = exp(trans), two n-tiles, resident forever ----
    uint32_t Bf0[8], Bf1[8], Bg0[8], Bg1[8];
    {
        const int jB0 = 16 * w + (lane >> 2);
        const int jB1 = jB0 + 8;
        const int kb  = 2 * (lane & 3);
#pragma unroll
        for (int kk = 0; kk < 8; kk++) {
            int k0 = 16 * kk + kb;
            Bf0[kk] = bfpack(__expf(trans[(k0)     * NN + jB0]),
                             __expf(trans[(k0 + 1) * NN + jB0]));
            Bf1[kk] = bfpack(__expf(trans[(k0 + 8) * NN + jB0]),
                             __expf(trans[(k0 + 9) * NN + jB0]));
            Bg0[kk] = bfpack(__expf(trans[(k0)     * NN + jB1]),
                             __expf(trans[(k0 + 1) * NN + jB1]));
            Bg1[kk] = bfpack(__expf(trans[(k0 + 8) * NN + jB1]),
                             __expf(trans[(k0 + 9) * NN + jB1]));
        }
    }

    // ---- zero both p buffers (pad rows stay zero forever) ----
    for (int i = tid; i < 2 * 16 * PITCH / 2; i += 256)
        ((uint32_t*)psh)[i] = 0u;

    const uint32_t psb = smem_u32(&psh[0][0]);

    // ---- init q0 = exp(s0 - s0[0]); step t=1 reads buffer 1 ----
    float qA0, qA1, qB0, qB1;      // this thread's 4 q values (tile0 x2, tile1 x2)
    {
        float2 ea = make_float2(0.f, 0.f), eb = make_float2(0.f, 0.f);
        if (real) {
            ea = *(const float2*)&em[((size_t)b * LL) * NN + jn0];
            eb = *(const float2*)&em[((size_t)b * LL) * NN + jn1];
        }
        float sA0 = start[jn0] + ea.x, sA1 = start[jn0 + 1] + ea.y;
        float sB0 = start[jn1] + eb.x, sB1 = start[jn1 + 1] + eb.y;
        if (w == 0 && c2 == 0 && real) { csh[r] = sA0; Lsh[r] = sA0; }
        __syncthreads();
        float c0 = csh[real ? r : 0];
        qA0 = __expf(sA0 - c0); qA1 = __expf(sA1 - c0);
        qB0 = __expf(sB0 - c0); qB1 = __expf(sB1 - c0);
        if (real) {
            *(uint32_t*)((char*)psh + BUFB + r * ROWB + jn0 * 2) = bfpack(qA0, qA1);
            *(uint32_t*)((char*)psh + BUFB + r * ROWB + jn1 * 2) = bfpack(qB0, qB1);
            if (w == 0 && c2 == 0) rinv[1][r] = 1.0f / qA0;
        }
    }

    // ---- prefetch t=1 ----
    float2 emA = make_float2(0.f, 0.f), emB = make_float2(0.f, 0.f);
    float mk = 1.0f;
    if (real) {
        emA = *(const float2*)&em[((size_t)b * LL + 1) * NN + jn0];
        emB = *(const float2*)&em[((size_t)b * LL + 1) * NN + jn1];
        mk = mask[b * LL + 1];
    }
    __syncthreads();

    for (int t = 1; t < LL; t++) {
        const int pr = t & 1, pw = pr ^ 1;

        // prefetch t+1
        float2 enA = make_float2(0.f, 0.f), enB = make_float2(0.f, 0.f);
        float mkn = 1.0f;
        if (real && t + 1 < LL) {
            enA = *(const float2*)&em[((size_t)b * LL + t + 1) * NN + jn0];
            enB = *(const float2*)&em[((size_t)b * LL + t + 1) * NN + jn1];
            mkn = mask[b * LL + t + 1];
        }

        // ---- MMA: tot = P @ E ; 4 chains (2 tiles x even/odd k) depth 4 ----
        float dA0 = 0.f, dA1 = 0.f, dA2 = 0.f, dA3 = 0.f;   // tile0 even k
        float eA0 = 0.f, eA1 = 0.f, eA2 = 0.f, eA3 = 0.f;   // tile0 odd  k
        float dB0 = 0.f, dB1 = 0.f, dB2 = 0.f, dB3 = 0.f;   // tile1 even k
        float eB0 = 0.f, eB1 = 0.f, eB2 = 0.f, eB3 = 0.f;   // tile1 odd  k
        {
            uint32_t abase = psb + (uint32_t)pr * BUFB
                           + (lane & 15) * ROWB + (lane >> 4) * 16;
#pragma unroll
            for (int kk = 0; kk < 8; kk += 2) {
                uint32_t a0, a1, a2, a3;
                ldm4(a0, a1, a2, a3, abase + kk * 32);
                mma16816(dA0, dA1, dA2, dA3, a0, a1, a2, a3, Bf0[kk], Bf1[kk]);
                mma16816(dB0, dB1, dB2, dB3, a0, a1, a2, a3, Bg0[kk], Bg1[kk]);
                uint32_t c0_, c1_, c2_, c3_;
                ldm4(c0_, c1_, c2_, c3_, abase + (kk + 1) * 32);
                mma16816(eA0, eA1, eA2, eA3, c0_, c1_, c2_, c3_, Bf0[kk + 1], Bf1[kk + 1]);
                mma16816(eB0, eB1, eB2, eB3, c0_, c1_, c2_, c3_, Bg0[kk + 1], Bg1[kk + 1]);
            }
        }
        float totA0 = dA0 + eA0, totA1 = dA1 + eA1;
        float totB0 = dB0 + eB0, totB1 = dB1 + eB1;
        (void)dA2; (void)dA3; (void)eA2; (void)eA3;
        (void)dB2; (void)dB3; (void)eB2; (void)eB3;

        // ---- epilogue (linear domain) ----
        float inv = rinv[pr][real ? r : 0];          // 1 / q_{t-1}[b][0]
        float qc0 = totA0 * __expf(emA.x) * inv;
        float qc1 = totA1 * __expf(emA.y) * inv;
        float qc2 = totB0 * __expf(emB.x) * inv;
        float qc3 = totB1 * __expf(emB.y) * inv;
        if (mk == 1.0f) {
            qA0 = qc0; qA1 = qc1; qB0 = qc2; qB1 = qc3;
        } else if (mk == 0.0f) {
            qA0 *= inv; qA1 *= inv; qB0 *= inv; qB1 *= inv;
        } else {
            qA0 = __expf(mk * __logf(qc0) + (1.0f - mk) * __logf(qA0 * inv));
            qA1 = __expf(mk * __logf(qc1) + (1.0f - mk) * __logf(qA1 * inv));
            qB0 = __expf(mk * __logf(qc2) + (1.0f - mk) * __logf(qB0 * inv));
            qB1 = __expf(mk * __logf(qc3) + (1.0f - mk) * __logf(qB1 * inv));
        }

        if (real) {
            if (w == 0 && c2 == 0) {
                Lsh[r] -= __logf(inv);               // L += log(q_{t-1}[0])
                rinv[pw][r] = 1.0f / qA0;
            }
            *(uint32_t*)((char*)psh + (uint32_t)pw * BUFB + r * ROWB + jn0 * 2)
                = bfpack(qA0, qA1);
            *(uint32_t*)((char*)psh + (uint32_t)pw * BUFB + r * ROWB + jn1 * 2)
                = bfpack(qB0, qB1);
        }
        emA = enA; emB = enB; mk = mkn;
        __syncthreads();
    }

    // ---- final: normalizer[b] = L[b] + log(sum_j q[b][j]) ----
    if (real) {
        sred[r][jn0]     = qA0;
        sred[r][jn0 + 1] = qA1;
        sred[r][jn1]     = qB0;
        sred[r][jn1 + 1] = qB1;
    }
    __syncthreads();
    if (w < RB) {
        float s = sred[w][lane] + sred[w][lane + 32] +
                  sred[w][lane + 64] + sred[w][lane + 96];
#pragma unroll
        for (int o = 16; o; o >>= 1)
            s += __shfl_xor_sync(0xffffffffu, s, o);
        if (lane == 0) g_norm[b0 + w] = Lsh[w] + __logf(s);
    }
}

// ---------------------------------------------------------------------------
// Path score. One block (128 threads) per batch.
// ---------------------------------------------------------------------------
__global__ __launch_bounds__(128)
void crf_path(const float* __restrict__ em,
              const int*   __restrict__ tgt,
              const float* __restrict__ mask,
              const float* __restrict__ start,
              const float* __restrict__ trans) {
    const int bb = blockIdx.x;
    const int tid = threadIdx.x;
    __shared__ float red[128];

    const size_t embase = (size_t)bb * LL * NN;
    float s = 0.0f;
    for (int t = tid; t < LL; t += 128) {
        if (t == 0) {
            int t0 = tgt[bb * LL];
            s += start[t0] + em[embase + t0];
        } else {
            int prev = tgt[bb * LL + t - 1];
            int cur  = tgt[bb * LL + t];
            s += mask[bb * LL + t] *
                 (trans[prev * NN + cur] + em[embase + (size_t)t * NN + cur]);
        }
    }
    red[tid] = s;
    __syncthreads();
#pragma unroll
    for (int o = 64; o; o >>= 1) {
        if (tid < o) red[tid] += red[tid + o];
        __syncthreads();
    }
    if (tid == 0) g_path[bb] = red[0];
}

// ---------------------------------------------------------------------------
// mean(normalizer - path)
// ---------------------------------------------------------------------------
__global__ __launch_bounds__(512)
void crf_final(float* __restrict__ out) {
    const int tid = threadIdx.x;
    __shared__ float wsum[16];
    float v = g_norm[tid] - g_path[tid];
#pragma unroll
    for (int o = 16; o; o >>= 1) v += __shfl_xor_sync(0xffffffffu, v, o);
    if ((tid & 31) == 0) wsum[tid >> 5] = v;
    __syncthreads();
    if (tid < 32) {
        float x = (tid < 16) ? wsum[tid] : 0.0f;
#pragma unroll
        for (int o = 8; o; o >>= 1) x += __shfl_xor_sync(0xffffffffu, x, o);
        if (tid == 0) out[0] = x * (1.0f / (float)BB);
    }
}

// ---------------------------------------------------------------------------
// Launch
// ---------------------------------------------------------------------------
extern "C" void kernel_launch(void* const* d_in, const int* in_sizes, int n_in,
                              void* d_out, int out_size) {
    const float* emission    = (const float*)d_in[0];
    const int*   target      = (const int*)  d_in[1];
    const float* mask        = (const float*)d_in[2];
    const float* start_trans = (const float*)d_in[3];
    const float* trans       = (const float*)d_in[4];
    float* out = (float*)d_out;

    crf_forward<<<BB / RB, 256>>>(emission, mask, start_trans, trans);
    crf_path<<<BB, 128>>>(emission, target, mask, start_trans, trans);
    crf_final<<<1, 512>>>(out);
}